// round 10
// baseline (speedup 1.0000x reference)
#include <cuda_runtime.h>
#include <cuda_fp16.h>
#include <float.h>

#define C_DIM 512
#define H_DIM 50
#define W_DIM 75
#define HW_DIM (H_DIM * W_DIM)
#define NROI 512
#define PRE 14
#define PADH 264   // stage row stride in halves (= 528B, 16B-aligned)

// channels-last fp16 copy of the feature map: [H*W, C]
__device__ __align__(16) __half g_featT[HW_DIM * C_DIM];

// -------------------------------------------------------------------------
// Tiled transpose + fp16 quantize: bottom [C, H*W] -> g_featT [H*W, C]
// -------------------------------------------------------------------------
__global__ void transpose_kernel(const float* __restrict__ in) {
    __shared__ float tile[64][33];
    int hw0 = blockIdx.x * 32;
    int c0  = blockIdx.y * 64;
    int tx = threadIdx.x, ty = threadIdx.y;

    #pragma unroll
    for (int j = 0; j < 64; j += 8) {
        int hw = hw0 + tx;
        int c  = c0 + ty + j;
        if (hw < HW_DIM) tile[ty + j][tx] = in[c * HW_DIM + hw];
    }
    __syncthreads();
    #pragma unroll
    for (int j = 0; j < 32; j += 8) {
        int hw = hw0 + ty + j;
        if (hw < HW_DIM) {
            __half2 v = __floats2half2_rn(tile[2 * tx][ty + j],
                                          tile[2 * tx + 1][ty + j]);
            *reinterpret_cast<__half2*>(&g_featT[hw * C_DIM + c0 + 2 * tx]) = v;
        }
    }
}

// accumulate one bilinear sample (4 corner uint4 regs) into m0..m3
__device__ __forceinline__ void acc_sample(
    const uint4& r00, const uint4& r01, const uint4& r10, const uint4& r11,
    float wy0, float wy1, float wx0, float wx1,
    __half2& m0, __half2& m1, __half2& m2, __half2& m3) {

    const __half2 w00 = __float2half2_rn(wy0 * wx0);
    const __half2 w01 = __float2half2_rn(wy0 * wx1);
    const __half2 w10 = __float2half2_rn(wy1 * wx0);
    const __half2 w11 = __float2half2_rn(wy1 * wx1);

    const __half2* h00 = reinterpret_cast<const __half2*>(&r00);
    const __half2* h01 = reinterpret_cast<const __half2*>(&r01);
    const __half2* h10 = reinterpret_cast<const __half2*>(&r10);
    const __half2* h11 = reinterpret_cast<const __half2*>(&r11);

    __half2 v0 = __hmul2(h00[0], w00);
    __half2 v1 = __hmul2(h00[1], w00);
    __half2 v2 = __hmul2(h00[2], w00);
    __half2 v3 = __hmul2(h00[3], w00);
    v0 = __hfma2(h01[0], w01, v0);
    v1 = __hfma2(h01[1], w01, v1);
    v2 = __hfma2(h01[2], w01, v2);
    v3 = __hfma2(h01[3], w01, v3);
    v0 = __hfma2(h10[0], w10, v0);
    v1 = __hfma2(h10[1], w10, v1);
    v2 = __hfma2(h10[2], w10, v2);
    v3 = __hfma2(h10[3], w10, v3);
    v0 = __hfma2(h11[0], w11, v0);
    v1 = __hfma2(h11[1], w11, v1);
    v2 = __hfma2(h11[2], w11, v2);
    v3 = __hfma2(h11[3], w11, v3);

    m0 = __hmax2(m0, v0);
    m1 = __hmax2(m1, v1);
    m2 = __hmax2(m2, v2);
    m3 = __hmax2(m3, v3);
}

// -------------------------------------------------------------------------
// Main kernel: grid (512 rois, 2 channel-halves), 128 threads (4 warps).
// Lane owns 8 consecutive channels (16B fp16 LDG.128); warp covers a
// 256-channel half; the 4 warps split the 49 output pixels round-robin.
// The 4 pre-pool samples per pixel are software-pipelined 2 deep.
// -------------------------------------------------------------------------
__global__ __launch_bounds__(128, 6) void roi_pool_kernel(
    const float* __restrict__ rois, float* __restrict__ out) {

    __shared__ float4 tabx[PRE], taby[PRE];
    __shared__ __align__(16) __half stage[49 * PADH];

    const int n = blockIdx.x;
    const int t = threadIdx.x;

    // ---- per-ROI corner tables (threads 0..27) ----
    if (t < 2 * PRE) {
        const int axis = (t >= PRE);          // 0 = x, 1 = y
        const int i = axis ? (t - PRE) : t;
        const float lo = rois[n * 5 + (axis ? 2 : 1)] * (1.0f / 16.0f);
        const float hi = rois[n * 5 + (axis ? 4 : 3)] * (1.0f / 16.0f);
        const int D = axis ? H_DIM : W_DIM;

        // replicate reference math exactly
        float s  = (hi - lo) / (float)(D - 1);
        float tt = (lo + hi - (float)(D - 1)) / (float)(D - 1);
        float base = -1.0f + (float)i * (2.0f / 13.0f);
        float g  = s * base + tt;
        float xc = (g + 1.0f) * 0.5f * (float)(D - 1);

        float f0 = floorf(xc);
        int   i0 = (int)f0;
        float w1 = xc - f0;
        float w0 = 1.0f - w1;
        float v0 = (i0 >= 0 && i0 <= D - 1) ? 1.0f : 0.0f;
        float v1 = (i0 + 1 >= 0 && i0 + 1 <= D - 1) ? 1.0f : 0.0f;
        int c0 = min(max(i0, 0), D - 1);
        int c1 = min(max(i0 + 1, 0), D - 1);

        int mul = axis ? (W_DIM * (C_DIM / 8)) : (C_DIM / 8);
        float4 e;
        e.x = __int_as_float(c0 * mul);
        e.y = __int_as_float(c1 * mul);
        e.z = w0 * v0;
        e.w = w1 * v1;
        if (axis) taby[i] = e; else tabx[i] = e;
    }
    __syncthreads();

    const int w    = t >> 5;
    const int lane = t & 31;
    const uint4* __restrict__ fb =
        (const uint4*)g_featT + blockIdx.y * 32 + lane;

    const __half2 HMIN = __float2half2_rn(-60000.0f);

    for (int p = w; p < 49; p += 4) {
        const int py = p / 7;
        const int px = p - py * 7;

        const float4 tx0 = tabx[2 * px];
        const float4 tx1 = tabx[2 * px + 1];
        const float4 ty0 = taby[2 * py];
        const float4 ty1 = taby[2 * py + 1];

        const int oy00 = __float_as_int(ty0.x), oy01 = __float_as_int(ty0.y);
        const int oy10 = __float_as_int(ty1.x), oy11 = __float_as_int(ty1.y);
        const int ox00 = __float_as_int(tx0.x), ox01 = __float_as_int(tx0.y);
        const int ox10 = __float_as_int(tx1.x), ox11 = __float_as_int(tx1.y);

        __half2 m0 = HMIN, m1 = HMIN, m2 = HMIN, m3 = HMIN;

        // ---- software-pipelined samples: s0(ty0,tx0) s1(ty0,tx1)
        //                                  s2(ty1,tx0) s3(ty1,tx1)
        // issue s0 + s1 gathers
        uint4 a00 = fb[oy00 + ox00];
        uint4 a01 = fb[oy00 + ox01];
        uint4 a10 = fb[oy01 + ox00];
        uint4 a11 = fb[oy01 + ox01];
        uint4 b00 = fb[oy00 + ox10];
        uint4 b01 = fb[oy00 + ox11];
        uint4 b10 = fb[oy01 + ox10];
        uint4 b11 = fb[oy01 + ox11];

        // compute s0, then refill a with s2
        acc_sample(a00, a01, a10, a11, ty0.z, ty0.w, tx0.z, tx0.w,
                   m0, m1, m2, m3);
        a00 = fb[oy10 + ox00];
        a01 = fb[oy10 + ox01];
        a10 = fb[oy11 + ox00];
        a11 = fb[oy11 + ox01];

        // compute s1, then refill b with s3
        acc_sample(b00, b01, b10, b11, ty0.z, ty0.w, tx1.z, tx1.w,
                   m0, m1, m2, m3);
        b00 = fb[oy10 + ox10];
        b01 = fb[oy10 + ox11];
        b10 = fb[oy11 + ox10];
        b11 = fb[oy11 + ox11];

        // compute s2, s3
        acc_sample(a00, a01, a10, a11, ty1.z, ty1.w, tx0.z, tx0.w,
                   m0, m1, m2, m3);
        acc_sample(b00, b01, b10, b11, ty1.z, ty1.w, tx1.z, tx1.w,
                   m0, m1, m2, m3);

        // pixel-major fp16 stage: 16B STS, lane-consecutive -> conflict-free
        uint4 pk;
        pk.x = *reinterpret_cast<unsigned int*>(&m0);
        pk.y = *reinterpret_cast<unsigned int*>(&m1);
        pk.z = *reinterpret_cast<unsigned int*>(&m2);
        pk.w = *reinterpret_cast<unsigned int*>(&m3);
        *reinterpret_cast<uint4*>(&stage[p * PADH + lane * 8]) = pk;
    }
    __syncthreads();

    // ---- coalesced writeback: thread handles a channel PAIR (2c, 2c+1) at
    // pixel p via one LDS.32; both STG streams coalesced. 6272 pairs total,
    // idx2 = t + k*128 walked incrementally (p fastest, 128 = 2*49 + 30).
    float* __restrict__ ob = out + (size_t)n * (C_DIM * 49)
                                 + (size_t)blockIdx.y * (256 * 49);
    int c2 = t / 49;
    int p  = t - c2 * 49;
    #pragma unroll 7
    for (int k = 0; k < 49; k++) {
        unsigned int v =
            *reinterpret_cast<const unsigned int*>(&stage[p * PADH + 2 * c2]);
        __half2 h = *reinterpret_cast<__half2*>(&v);
        float2 f = __half22float2(h);
        ob[(2 * c2) * 49 + p]     = f.x;
        ob[(2 * c2 + 1) * 49 + p] = f.y;
        p += 30; c2 += 2;             // advance by 128 = 2*49 + 30
        if (p >= 49) { p -= 49; c2 += 1; }
    }
}

// -------------------------------------------------------------------------
extern "C" void kernel_launch(void* const* d_in, const int* in_sizes, int n_in,
                              void* d_out, int out_size) {
    const float* bottom = (const float*)d_in[0];
    const float* rois   = (const float*)d_in[1];
    if (n_in >= 2 && in_sizes[0] == NROI * 5) {
        bottom = (const float*)d_in[1];
        rois   = (const float*)d_in[0];
    }
    float* out = (float*)d_out;

    dim3 tgrid((HW_DIM + 31) / 32, C_DIM / 64);
    transpose_kernel<<<tgrid, dim3(32, 8)>>>(bottom);

    dim3 rgrid(NROI, 2);
    roi_pool_kernel<<<rgrid, 128>>>(rois, out);
}